// round 13
// baseline (speedup 1.0000x reference)
#include <cuda_runtime.h>
#include <cuda_bf16.h>
#include <cstdint>

// Problem constants
#define Bn  4
#define Sn  1024
#define Dn  1024
#define Hn  16
#define DHn 64
#define Mtot (Bn * Sn)   // 4096

// Scratch (device globals: allocation is forbidden)
__device__ __align__(16) float g_Q[(size_t)Bn * Hn * Sn * DHn];   // [B,H,S,DH]
__device__ __align__(16) float g_K[(size_t)Bn * Hn * Sn * DHn];
__device__ __align__(16) float g_V[(size_t)Bn * Hn * Sn * DHn];
__device__ __align__(16) float g_S[(size_t)Bn * Hn * Sn * Sn];    // scores/probs [B,H,S,S] (256MB)
__device__ __align__(16) float g_C[(size_t)Bn * Sn * Dn];         // context [B,S,D]

// ---- packed f32x2 helpers (sm_103a) ----
#define PACK2(dst, x) asm("mov.b64 %0, {%1, %2};" : "=l"(dst) : "f"(x), "f"(x))
#define FMA2(acc, a, b) asm("fma.rn.f32x2 %0, %1, %2, %0;" : "+l"(acc) : "l"(a), "l"(b))

__device__ __forceinline__ float lo32(unsigned long long u) {
    return __uint_as_float((unsigned)(u & 0xffffffffull));
}
__device__ __forceinline__ float hi32(unsigned long long u) {
    return __uint_as_float((unsigned)(u >> 32));
}

// ============================================================================
// Generic 128x64-tile fp32 GEMM using packed FFMA2.
// MODE 0: QKV projection. grid = (H=16, Mtot/128=32). A = x [4096,1024],
//         B = W + h*D*DH (row stride 64), C = g_Q/g_K/g_V per `sel`,
//         layout [B,H,S,DH], bias bq[h*64+n].
// MODE 1: AV. grid = (S/128=8, B*H=64). A = g_S[bh] [1024,1024],
//         B = g_V[bh] [1024,64], C = g_C [B,S,D] at column h*64.
// MODE 2: output projection. grid = (D/64=16, Mtot/128=32). A = g_C,
//         B = Wo (ldb=1024), C = d_out, bias bo.
// ============================================================================
template <int MODE>
__global__ void __launch_bounds__(256, 2) gemm_f32x2(
    const float* __restrict__ Ain, const float* __restrict__ Bin,
    const float* __restrict__ bias, float* __restrict__ Cout, int sel)
{
    const int tid = threadIdx.x;

    int mt, bh = 0, h = 0, nt = 0;
    const float* Aptr;
    const float* Bptr;
    int ldb;
    if (MODE == 0) {
        h = blockIdx.x; mt = blockIdx.y;
        Aptr = Ain;
        Bptr = Bin + (size_t)h * Dn * DHn;
        ldb = DHn;
    } else if (MODE == 1) {
        mt = blockIdx.x; bh = blockIdx.y;
        Aptr = g_S + (size_t)bh * Sn * Sn;
        Bptr = g_V + (size_t)bh * Sn * DHn;
        ldb = DHn;
    } else {
        nt = blockIdx.x; mt = blockIdx.y;
        Aptr = g_C;
        Bptr = Bin + nt * 64;
        ldb = Dn;
    }
    const int lda = 1024;  // all A matrices here have 1024 columns

    __shared__ __align__(16) float As[16][132];  // transposed A tile [k][m], padded
    __shared__ __align__(16) float Bs[16][64];

    const int ty = tid >> 4;        // 0..15 -> m offset ty*8
    const int tx = tid & 15;        // 0..15 -> n offset tx*4

    unsigned long long acc[4][4];
#pragma unroll
    for (int i = 0; i < 4; i++)
#pragma unroll
        for (int j = 0; j < 4; j++) acc[i][j] = 0ull;

    const int m0 = mt * 128;
    const int arow = tid >> 2;          // 0..63
    const int acol = (tid & 3) * 4;     // 0,4,8,12
    const int brow = tid >> 4;          // 0..15
    const int bcol = (tid & 15) * 4;    // 0..60

    for (int k0 = 0; k0 < 1024; k0 += 16) {
        // Load A tile (128x16), store transposed into As[k][m]
#pragma unroll
        for (int p = 0; p < 2; p++) {
            const int r = arow + p * 64;
            float4 v = *reinterpret_cast<const float4*>(
                &Aptr[(size_t)(m0 + r) * lda + k0 + acol]);
            As[acol + 0][r] = v.x;
            As[acol + 1][r] = v.y;
            As[acol + 2][r] = v.z;
            As[acol + 3][r] = v.w;
        }
        // Load B tile (16x64)
        {
            float4 w = *reinterpret_cast<const float4*>(
                &Bptr[(size_t)(k0 + brow) * ldb + bcol]);
            *reinterpret_cast<float4*>(&Bs[brow][bcol]) = w;
        }
        __syncthreads();

#pragma unroll
        for (int k = 0; k < 16; k++) {
            ulonglong2 a01 = *reinterpret_cast<const ulonglong2*>(&As[k][ty * 8]);
            ulonglong2 a23 = *reinterpret_cast<const ulonglong2*>(&As[k][ty * 8 + 4]);
            float4 bv = *reinterpret_cast<const float4*>(&Bs[k][tx * 4]);
            unsigned long long b0, b1, b2, b3;
            PACK2(b0, bv.x); PACK2(b1, bv.y); PACK2(b2, bv.z); PACK2(b3, bv.w);
            FMA2(acc[0][0], a01.x, b0); FMA2(acc[0][1], a01.x, b1);
            FMA2(acc[0][2], a01.x, b2); FMA2(acc[0][3], a01.x, b3);
            FMA2(acc[1][0], a01.y, b0); FMA2(acc[1][1], a01.y, b1);
            FMA2(acc[1][2], a01.y, b2); FMA2(acc[1][3], a01.y, b3);
            FMA2(acc[2][0], a23.x, b0); FMA2(acc[2][1], a23.x, b1);
            FMA2(acc[2][2], a23.x, b2); FMA2(acc[2][3], a23.x, b3);
            FMA2(acc[3][0], a23.y, b0); FMA2(acc[3][1], a23.y, b1);
            FMA2(acc[3][2], a23.y, b2); FMA2(acc[3][3], a23.y, b3);
        }
        __syncthreads();
    }

    // bias (MODE 0 and 2)
    float4 bias4 = make_float4(0.f, 0.f, 0.f, 0.f);
    if (MODE == 0)
        bias4 = *reinterpret_cast<const float4*>(&bias[h * 64 + tx * 4]);
    else if (MODE == 2)
        bias4 = *reinterpret_cast<const float4*>(&bias[nt * 64 + tx * 4]);

    // Epilogue: 8 rows x 4 cols per thread; acc[i2] holds row pair (2*i2, 2*i2+1)
#pragma unroll
    for (int i2 = 0; i2 < 4; i2++) {
        const int rloc = ty * 8 + i2 * 2;
        float4 row_lo = make_float4(lo32(acc[i2][0]) + bias4.x,
                                    lo32(acc[i2][1]) + bias4.y,
                                    lo32(acc[i2][2]) + bias4.z,
                                    lo32(acc[i2][3]) + bias4.w);
        float4 row_hi = make_float4(hi32(acc[i2][0]) + bias4.x,
                                    hi32(acc[i2][1]) + bias4.y,
                                    hi32(acc[i2][2]) + bias4.z,
                                    hi32(acc[i2][3]) + bias4.w);
        if (MODE == 0) {
            float* dst = (sel == 0) ? g_Q : (sel == 1) ? g_K : g_V;
            const int m_a = m0 + rloc;
            const int b_a = m_a >> 10, s_a = m_a & 1023;
            const int m_b = m_a + 1;
            const int b_b = m_b >> 10, s_b = m_b & 1023;
            size_t ia = (((size_t)(b_a * Hn + h) * Sn + s_a) << 6) + tx * 4;
            size_t ib = (((size_t)(b_b * Hn + h) * Sn + s_b) << 6) + tx * 4;
            *reinterpret_cast<float4*>(&dst[ia]) = row_lo;
            *reinterpret_cast<float4*>(&dst[ib]) = row_hi;
        } else if (MODE == 1) {
            const int b = bh >> 4, hh = bh & 15;
            const int s = m0 + rloc;
            size_t ia = ((size_t)(b * Sn + s)) * Dn + hh * 64 + tx * 4;
            size_t ib = ((size_t)(b * Sn + s + 1)) * Dn + hh * 64 + tx * 4;
            *reinterpret_cast<float4*>(&g_C[ia]) = row_lo;
            *reinterpret_cast<float4*>(&g_C[ib]) = row_hi;
        } else {
            const int m = m0 + rloc;
            size_t ia = (size_t)m * Dn + nt * 64 + tx * 4;
            size_t ib = (size_t)(m + 1) * Dn + nt * 64 + tx * 4;
            *reinterpret_cast<float4*>(&Cout[ia]) = row_lo;
            *reinterpret_cast<float4*>(&Cout[ib]) = row_hi;
        }
    }
}

// ============================================================================
// scores[s][t] = dot(Q[bh,s,:], K[bh,t,:]) * 0.125, zeroed for s >= len[b].
// grid = (16 t-tiles, 16 s-tiles, B*H). 64x64 output tile, full K=64 in smem.
// ============================================================================
__global__ void __launch_bounds__(256, 2) scores_kernel(const int* __restrict__ lens)
{
    const int tid = threadIdx.x;
    const int bh = blockIdx.z;
    const int b = bh >> 4;
    const int st = blockIdx.y, tt = blockIdx.x;

    const float* Qb = g_Q + ((size_t)bh * Sn + st * 64) * DHn;
    const float* Kb = g_K + ((size_t)bh * Sn + tt * 64) * DHn;

    __shared__ __align__(16) float Qs[64][68];  // transposed [e][s]
    __shared__ __align__(16) float Ks[64][68];  // transposed [e][t]

    const int lr = tid >> 4;         // 0..15
    const int lc = (tid & 15) * 4;   // 0..60
#pragma unroll
    for (int p = 0; p < 4; p++) {
        const int r = lr + p * 16;
        float4 q = *reinterpret_cast<const float4*>(&Qb[r * 64 + lc]);
        Qs[lc + 0][r] = q.x; Qs[lc + 1][r] = q.y;
        Qs[lc + 2][r] = q.z; Qs[lc + 3][r] = q.w;
        float4 kk = *reinterpret_cast<const float4*>(&Kb[r * 64 + lc]);
        Ks[lc + 0][r] = kk.x; Ks[lc + 1][r] = kk.y;
        Ks[lc + 2][r] = kk.z; Ks[lc + 3][r] = kk.w;
    }
    __syncthreads();

    const int s0 = (tid >> 4) * 4;  // 0..60
    const int t0 = (tid & 15) * 4;  // 0..60

    unsigned long long acc[2][4];
#pragma unroll
    for (int i = 0; i < 2; i++)
#pragma unroll
        for (int j = 0; j < 4; j++) acc[i][j] = 0ull;

#pragma unroll 16
    for (int k = 0; k < 64; k++) {
        ulonglong2 aa = *reinterpret_cast<const ulonglong2*>(&Qs[k][s0]);
        float4 kv = *reinterpret_cast<const float4*>(&Ks[k][t0]);
        unsigned long long b0, b1, b2, b3;
        PACK2(b0, kv.x); PACK2(b1, kv.y); PACK2(b2, kv.z); PACK2(b3, kv.w);
        FMA2(acc[0][0], aa.x, b0); FMA2(acc[0][1], aa.x, b1);
        FMA2(acc[0][2], aa.x, b2); FMA2(acc[0][3], aa.x, b3);
        FMA2(acc[1][0], aa.y, b0); FMA2(acc[1][1], aa.y, b1);
        FMA2(acc[1][2], aa.y, b2); FMA2(acc[1][3], aa.y, b3);
    }

    const int len = lens[b];
    float* outbase = g_S + ((size_t)bh << 20) + (size_t)tt * 64 + t0;
#pragma unroll
    for (int i2 = 0; i2 < 2; i2++) {
        const int r_lo = s0 + i2 * 2;
        const int sg_lo = st * 64 + r_lo;
        const int sg_hi = sg_lo + 1;
        const float sc_lo = (sg_lo < len) ? 0.125f : 0.0f;
        const float sc_hi = (sg_hi < len) ? 0.125f : 0.0f;
        float4 v_lo = make_float4(lo32(acc[i2][0]) * sc_lo, lo32(acc[i2][1]) * sc_lo,
                                  lo32(acc[i2][2]) * sc_lo, lo32(acc[i2][3]) * sc_lo);
        float4 v_hi = make_float4(hi32(acc[i2][0]) * sc_hi, hi32(acc[i2][1]) * sc_hi,
                                  hi32(acc[i2][2]) * sc_hi, hi32(acc[i2][3]) * sc_hi);
        *reinterpret_cast<float4*>(&outbase[(size_t)sg_lo * Sn]) = v_lo;
        *reinterpret_cast<float4*>(&outbase[(size_t)sg_hi * Sn]) = v_hi;
    }
}

// ============================================================================
// Row softmax over 1024 keys, in place in g_S. One block (128 thr) per row.
// Masked rows are all-zero -> max 0, exp 1, sum 1024 -> uniform 1/1024,
// exactly matching the reference (mask-then-softmax).
// ============================================================================
__global__ void __launch_bounds__(128) softmax_kernel()
{
    const int tid = threadIdx.x;
    float4* p = reinterpret_cast<float4*>(g_S + (size_t)blockIdx.x * Sn);
    float4 v0 = p[tid];
    float4 v1 = p[tid + 128];

    float m = fmaxf(fmaxf(fmaxf(v0.x, v0.y), fmaxf(v0.z, v0.w)),
                    fmaxf(fmaxf(v1.x, v1.y), fmaxf(v1.z, v1.w)));
#pragma unroll
    for (int o = 16; o > 0; o >>= 1)
        m = fmaxf(m, __shfl_xor_sync(0xffffffffu, m, o));

    __shared__ float redm[4];
    __shared__ float reds[4];
    const int w = tid >> 5;
    if ((tid & 31) == 0) redm[w] = m;
    __syncthreads();
    m = fmaxf(fmaxf(redm[0], redm[1]), fmaxf(redm[2], redm[3]));

    v0.x = __expf(v0.x - m); v0.y = __expf(v0.y - m);
    v0.z = __expf(v0.z - m); v0.w = __expf(v0.w - m);
    v1.x = __expf(v1.x - m); v1.y = __expf(v1.y - m);
    v1.z = __expf(v1.z - m); v1.w = __expf(v1.w - m);

    float s = (v0.x + v0.y) + (v0.z + v0.w) + (v1.x + v1.y) + (v1.z + v1.w);
#pragma unroll
    for (int o = 16; o > 0; o >>= 1)
        s += __shfl_xor_sync(0xffffffffu, s, o);
    if ((tid & 31) == 0) reds[w] = s;
    __syncthreads();
    s = (reds[0] + reds[1]) + (reds[2] + reds[3]);

    const float inv = 1.0f / s;
    v0.x *= inv; v0.y *= inv; v0.z *= inv; v0.w *= inv;
    v1.x *= inv; v1.y *= inv; v1.z *= inv; v1.w *= inv;
    p[tid] = v0;
    p[tid + 128] = v1;
}

// ============================================================================
extern "C" void kernel_launch(void* const* d_in, const int* in_sizes, int n_in,
                              void* d_out, int out_size)
{
    const float* xq  = (const float*)d_in[0];
    const float* xk  = (const float*)d_in[1];
    const float* xv  = (const float*)d_in[2];
    const int*   len = (const int*)  d_in[3];
    const float* Wq  = (const float*)d_in[4];
    const float* bq  = (const float*)d_in[5];
    const float* Wk  = (const float*)d_in[6];
    const float* bk  = (const float*)d_in[7];
    const float* Wv  = (const float*)d_in[8];
    const float* bv  = (const float*)d_in[9];
    const float* Wo  = (const float*)d_in[10];
    const float* bo  = (const float*)d_in[11];
    float* out = (float*)d_out;

    // 1) Q/K/V projections -> g_Q/g_K/g_V in [B,H,S,DH]
    gemm_f32x2<0><<<dim3(Hn, Mtot / 128), 256>>>(xq, Wq, bq, nullptr, 0);
    gemm_f32x2<0><<<dim3(Hn, Mtot / 128), 256>>>(xk, Wk, bk, nullptr, 1);
    gemm_f32x2<0><<<dim3(Hn, Mtot / 128), 256>>>(xv, Wv, bv, nullptr, 2);

    // 2) scores = QK^T / 8, query-row-masked -> g_S
    scores_kernel<<<dim3(Sn / 64, Sn / 64, Bn * Hn), 256>>>(len);

    // 3) softmax over keys, in place
    softmax_kernel<<<Bn * Hn * Sn, 128>>>();

    // 4) context = P @ V -> g_C in [B,S,D] (heads concatenated)
    gemm_f32x2<1><<<dim3(Sn / 128, Bn * Hn), 256>>>(nullptr, nullptr, nullptr, nullptr, 0);

    // 5) out = context @ Wo + bo
    gemm_f32x2<2><<<dim3(Dn / 64, Mtot / 128), 256>>>(nullptr, Wo, bo, out, 0);
}

// round 14
// speedup vs baseline: 1.0017x; 1.0017x over previous
#include <cuda_runtime.h>
#include <cuda_bf16.h>
#include <cstdint>

// Problem constants
#define Bn  4
#define Sn  1024
#define Dn  1024
#define Hn  16
#define DHn 64
#define Mtot (Bn * Sn)   // 4096

// Scratch (device globals: allocation is forbidden)
__device__ __align__(16) float g_Q[(size_t)Bn * Hn * Sn * DHn];   // [B,H,S,DH]
__device__ __align__(16) float g_K[(size_t)Bn * Hn * Sn * DHn];
__device__ __align__(16) float g_V[(size_t)Bn * Hn * Sn * DHn];
__device__ __align__(16) float g_S[(size_t)Bn * Hn * Sn * Sn];    // scores/probs [B,H,S,S] (256MB)
__device__ __align__(16) float g_C[(size_t)Bn * Sn * Dn];         // context [B,S,D]

// ---- packed f32x2 helpers (sm_103a) ----
#define PACK2(dst, x) asm("mov.b64 %0, {%1, %2};" : "=l"(dst) : "f"(x), "f"(x))
#define FMA2(acc, a, b) asm("fma.rn.f32x2 %0, %1, %2, %0;" : "+l"(acc) : "l"(a), "l"(b))

__device__ __forceinline__ float lo32(unsigned long long u) {
    return __uint_as_float((unsigned)(u & 0xffffffffull));
}
__device__ __forceinline__ float hi32(unsigned long long u) {
    return __uint_as_float((unsigned)(u >> 32));
}

// ============================================================================
// Generic 128x64-tile fp32 GEMM using packed FFMA2.
// MODE 0: QKV projection. grid = (H=16, Mtot/128=32). A = x [4096,1024],
//         B = W + h*D*DH (row stride 64), C = g_Q/g_K/g_V per `sel`,
//         layout [B,H,S,DH], bias bq[h*64+n].
// MODE 1: AV. grid = (S/128=8, B*H=64). A = g_S[bh] [1024,1024],
//         B = g_V[bh] [1024,64], C = g_C [B,S,D] at column h*64.
// MODE 2: output projection. grid = (D/64=16, Mtot/128=32). A = g_C,
//         B = Wo (ldb=1024), C = d_out, bias bo.
// ============================================================================
template <int MODE>
__global__ void __launch_bounds__(256, 2) gemm_f32x2(
    const float* __restrict__ Ain, const float* __restrict__ Bin,
    const float* __restrict__ bias, float* __restrict__ Cout, int sel)
{
    const int tid = threadIdx.x;

    int mt, bh = 0, h = 0, nt = 0;
    const float* Aptr;
    const float* Bptr;
    int ldb;
    if (MODE == 0) {
        h = blockIdx.x; mt = blockIdx.y;
        Aptr = Ain;
        Bptr = Bin + (size_t)h * Dn * DHn;
        ldb = DHn;
    } else if (MODE == 1) {
        mt = blockIdx.x; bh = blockIdx.y;
        Aptr = g_S + (size_t)bh * Sn * Sn;
        Bptr = g_V + (size_t)bh * Sn * DHn;
        ldb = DHn;
    } else {
        nt = blockIdx.x; mt = blockIdx.y;
        Aptr = g_C;
        Bptr = Bin + nt * 64;
        ldb = Dn;
    }
    const int lda = 1024;  // all A matrices here have 1024 columns

    __shared__ __align__(16) float As[16][132];  // transposed A tile [k][m], padded
    __shared__ __align__(16) float Bs[16][64];

    const int ty = tid >> 4;        // 0..15 -> m offset ty*8
    const int tx = tid & 15;        // 0..15 -> n offset tx*4

    unsigned long long acc[4][4];
#pragma unroll
    for (int i = 0; i < 4; i++)
#pragma unroll
        for (int j = 0; j < 4; j++) acc[i][j] = 0ull;

    const int m0 = mt * 128;
    const int arow = tid >> 2;          // 0..63
    const int acol = (tid & 3) * 4;     // 0,4,8,12
    const int brow = tid >> 4;          // 0..15
    const int bcol = (tid & 15) * 4;    // 0..60

    for (int k0 = 0; k0 < 1024; k0 += 16) {
        // Load A tile (128x16), store transposed into As[k][m]
#pragma unroll
        for (int p = 0; p < 2; p++) {
            const int r = arow + p * 64;
            float4 v = *reinterpret_cast<const float4*>(
                &Aptr[(size_t)(m0 + r) * lda + k0 + acol]);
            As[acol + 0][r] = v.x;
            As[acol + 1][r] = v.y;
            As[acol + 2][r] = v.z;
            As[acol + 3][r] = v.w;
        }
        // Load B tile (16x64)
        {
            float4 w = *reinterpret_cast<const float4*>(
                &Bptr[(size_t)(k0 + brow) * ldb + bcol]);
            *reinterpret_cast<float4*>(&Bs[brow][bcol]) = w;
        }
        __syncthreads();

#pragma unroll
        for (int k = 0; k < 16; k++) {
            ulonglong2 a01 = *reinterpret_cast<const ulonglong2*>(&As[k][ty * 8]);
            ulonglong2 a23 = *reinterpret_cast<const ulonglong2*>(&As[k][ty * 8 + 4]);
            float4 bv = *reinterpret_cast<const float4*>(&Bs[k][tx * 4]);
            unsigned long long b0, b1, b2, b3;
            PACK2(b0, bv.x); PACK2(b1, bv.y); PACK2(b2, bv.z); PACK2(b3, bv.w);
            FMA2(acc[0][0], a01.x, b0); FMA2(acc[0][1], a01.x, b1);
            FMA2(acc[0][2], a01.x, b2); FMA2(acc[0][3], a01.x, b3);
            FMA2(acc[1][0], a01.y, b0); FMA2(acc[1][1], a01.y, b1);
            FMA2(acc[1][2], a01.y, b2); FMA2(acc[1][3], a01.y, b3);
            FMA2(acc[2][0], a23.x, b0); FMA2(acc[2][1], a23.x, b1);
            FMA2(acc[2][2], a23.x, b2); FMA2(acc[2][3], a23.x, b3);
            FMA2(acc[3][0], a23.y, b0); FMA2(acc[3][1], a23.y, b1);
            FMA2(acc[3][2], a23.y, b2); FMA2(acc[3][3], a23.y, b3);
        }
        __syncthreads();
    }

    // bias (MODE 0 and 2)
    float4 bias4 = make_float4(0.f, 0.f, 0.f, 0.f);
    if (MODE == 0)
        bias4 = *reinterpret_cast<const float4*>(&bias[h * 64 + tx * 4]);
    else if (MODE == 2)
        bias4 = *reinterpret_cast<const float4*>(&bias[nt * 64 + tx * 4]);

    // Epilogue: 8 rows x 4 cols per thread; acc[i2] holds row pair (2*i2, 2*i2+1)
#pragma unroll
    for (int i2 = 0; i2 < 4; i2++) {
        const int rloc = ty * 8 + i2 * 2;
        float4 row_lo = make_float4(lo32(acc[i2][0]) + bias4.x,
                                    lo32(acc[i2][1]) + bias4.y,
                                    lo32(acc[i2][2]) + bias4.z,
                                    lo32(acc[i2][3]) + bias4.w);
        float4 row_hi = make_float4(hi32(acc[i2][0]) + bias4.x,
                                    hi32(acc[i2][1]) + bias4.y,
                                    hi32(acc[i2][2]) + bias4.z,
                                    hi32(acc[i2][3]) + bias4.w);
        if (MODE == 0) {
            float* dst = (sel == 0) ? g_Q : (sel == 1) ? g_K : g_V;
            const int m_a = m0 + rloc;
            const int b_a = m_a >> 10, s_a = m_a & 1023;
            const int m_b = m_a + 1;
            const int b_b = m_b >> 10, s_b = m_b & 1023;
            size_t ia = (((size_t)(b_a * Hn + h) * Sn + s_a) << 6) + tx * 4;
            size_t ib = (((size_t)(b_b * Hn + h) * Sn + s_b) << 6) + tx * 4;
            *reinterpret_cast<float4*>(&dst[ia]) = row_lo;
            *reinterpret_cast<float4*>(&dst[ib]) = row_hi;
        } else if (MODE == 1) {
            const int b = bh >> 4, hh = bh & 15;
            const int s = m0 + rloc;
            size_t ia = ((size_t)(b * Sn + s)) * Dn + hh * 64 + tx * 4;
            size_t ib = ((size_t)(b * Sn + s + 1)) * Dn + hh * 64 + tx * 4;
            *reinterpret_cast<float4*>(&g_C[ia]) = row_lo;
            *reinterpret_cast<float4*>(&g_C[ib]) = row_hi;
        } else {
            const int m = m0 + rloc;
            size_t ia = (size_t)m * Dn + nt * 64 + tx * 4;
            size_t ib = (size_t)(m + 1) * Dn + nt * 64 + tx * 4;
            *reinterpret_cast<float4*>(&Cout[ia]) = row_lo;
            *reinterpret_cast<float4*>(&Cout[ib]) = row_hi;
        }
    }
}

// ============================================================================
// scores[s][t] = dot(Q[bh,s,:], K[bh,t,:]) * 0.125, zeroed for s >= len[b].
// grid = (16 t-tiles, 16 s-tiles, B*H). 64x64 output tile, full K=64 in smem.
// ============================================================================
__global__ void __launch_bounds__(256, 2) scores_kernel(const int* __restrict__ lens)
{
    const int tid = threadIdx.x;
    const int bh = blockIdx.z;
    const int b = bh >> 4;
    const int st = blockIdx.y, tt = blockIdx.x;

    const float* Qb = g_Q + ((size_t)bh * Sn + st * 64) * DHn;
    const float* Kb = g_K + ((size_t)bh * Sn + tt * 64) * DHn;

    __shared__ __align__(16) float Qs[64][68];  // transposed [e][s]
    __shared__ __align__(16) float Ks[64][68];  // transposed [e][t]

    const int lr = tid >> 4;         // 0..15
    const int lc = (tid & 15) * 4;   // 0..60
#pragma unroll
    for (int p = 0; p < 4; p++) {
        const int r = lr + p * 16;
        float4 q = *reinterpret_cast<const float4*>(&Qb[r * 64 + lc]);
        Qs[lc + 0][r] = q.x; Qs[lc + 1][r] = q.y;
        Qs[lc + 2][r] = q.z; Qs[lc + 3][r] = q.w;
        float4 kk = *reinterpret_cast<const float4*>(&Kb[r * 64 + lc]);
        Ks[lc + 0][r] = kk.x; Ks[lc + 1][r] = kk.y;
        Ks[lc + 2][r] = kk.z; Ks[lc + 3][r] = kk.w;
    }
    __syncthreads();

    const int s0 = (tid >> 4) * 4;  // 0..60
    const int t0 = (tid & 15) * 4;  // 0..60

    unsigned long long acc[2][4];
#pragma unroll
    for (int i = 0; i < 2; i++)
#pragma unroll
        for (int j = 0; j < 4; j++) acc[i][j] = 0ull;

#pragma unroll 16
    for (int k = 0; k < 64; k++) {
        ulonglong2 aa = *reinterpret_cast<const ulonglong2*>(&Qs[k][s0]);
        float4 kv = *reinterpret_cast<const float4*>(&Ks[k][t0]);
        unsigned long long b0, b1, b2, b3;
        PACK2(b0, kv.x); PACK2(b1, kv.y); PACK2(b2, kv.z); PACK2(b3, kv.w);
        FMA2(acc[0][0], aa.x, b0); FMA2(acc[0][1], aa.x, b1);
        FMA2(acc[0][2], aa.x, b2); FMA2(acc[0][3], aa.x, b3);
        FMA2(acc[1][0], aa.y, b0); FMA2(acc[1][1], aa.y, b1);
        FMA2(acc[1][2], aa.y, b2); FMA2(acc[1][3], aa.y, b3);
    }

    const int len = lens[b];
    float* outbase = g_S + ((size_t)bh << 20) + (size_t)tt * 64 + t0;
#pragma unroll
    for (int i2 = 0; i2 < 2; i2++) {
        const int r_lo = s0 + i2 * 2;
        const int sg_lo = st * 64 + r_lo;
        const int sg_hi = sg_lo + 1;
        const float sc_lo = (sg_lo < len) ? 0.125f : 0.0f;
        const float sc_hi = (sg_hi < len) ? 0.125f : 0.0f;
        float4 v_lo = make_float4(lo32(acc[i2][0]) * sc_lo, lo32(acc[i2][1]) * sc_lo,
                                  lo32(acc[i2][2]) * sc_lo, lo32(acc[i2][3]) * sc_lo);
        float4 v_hi = make_float4(hi32(acc[i2][0]) * sc_hi, hi32(acc[i2][1]) * sc_hi,
                                  hi32(acc[i2][2]) * sc_hi, hi32(acc[i2][3]) * sc_hi);
        *reinterpret_cast<float4*>(&outbase[(size_t)sg_lo * Sn]) = v_lo;
        *reinterpret_cast<float4*>(&outbase[(size_t)sg_hi * Sn]) = v_hi;
    }
}

// ============================================================================
// Row softmax over 1024 keys, in place in g_S. One block (128 thr) per row.
// Masked rows are all-zero -> max 0, exp 1, sum 1024 -> uniform 1/1024,
// exactly matching the reference (mask-then-softmax).
// ============================================================================
__global__ void __launch_bounds__(128) softmax_kernel()
{
    const int tid = threadIdx.x;
    float4* p = reinterpret_cast<float4*>(g_S + (size_t)blockIdx.x * Sn);
    float4 v0 = p[tid];
    float4 v1 = p[tid + 128];

    float m = fmaxf(fmaxf(fmaxf(v0.x, v0.y), fmaxf(v0.z, v0.w)),
                    fmaxf(fmaxf(v1.x, v1.y), fmaxf(v1.z, v1.w)));
#pragma unroll
    for (int o = 16; o > 0; o >>= 1)
        m = fmaxf(m, __shfl_xor_sync(0xffffffffu, m, o));

    __shared__ float redm[4];
    __shared__ float reds[4];
    const int w = tid >> 5;
    if ((tid & 31) == 0) redm[w] = m;
    __syncthreads();
    m = fmaxf(fmaxf(redm[0], redm[1]), fmaxf(redm[2], redm[3]));

    v0.x = __expf(v0.x - m); v0.y = __expf(v0.y - m);
    v0.z = __expf(v0.z - m); v0.w = __expf(v0.w - m);
    v1.x = __expf(v1.x - m); v1.y = __expf(v1.y - m);
    v1.z = __expf(v1.z - m); v1.w = __expf(v1.w - m);

    float s = (v0.x + v0.y) + (v0.z + v0.w) + (v1.x + v1.y) + (v1.z + v1.w);
#pragma unroll
    for (int o = 16; o > 0; o >>= 1)
        s += __shfl_xor_sync(0xffffffffu, s, o);
    if ((tid & 31) == 0) reds[w] = s;
    __syncthreads();
    s = (reds[0] + reds[1]) + (reds[2] + reds[3]);

    const float inv = 1.0f / s;
    v0.x *= inv; v0.y *= inv; v0.z *= inv; v0.w *= inv;
    v1.x *= inv; v1.y *= inv; v1.z *= inv; v1.w *= inv;
    p[tid] = v0;
    p[tid + 128] = v1;
}

// ============================================================================
extern "C" void kernel_launch(void* const* d_in, const int* in_sizes, int n_in,
                              void* d_out, int out_size)
{
    const float* xq  = (const float*)d_in[0];
    const float* xk  = (const float*)d_in[1];
    const float* xv  = (const float*)d_in[2];
    const int*   len = (const int*)  d_in[3];
    const float* Wq  = (const float*)d_in[4];
    const float* bq  = (const float*)d_in[5];
    const float* Wk  = (const float*)d_in[6];
    const float* bk  = (const float*)d_in[7];
    const float* Wv  = (const float*)d_in[8];
    const float* bv  = (const float*)d_in[9];
    const float* Wo  = (const float*)d_in[10];
    const float* bo  = (const float*)d_in[11];
    float* out = (float*)d_out;

    // 1) Q/K/V projections -> g_Q/g_K/g_V in [B,H,S,DH]
    gemm_f32x2<0><<<dim3(Hn, Mtot / 128), 256>>>(xq, Wq, bq, nullptr, 0);
    gemm_f32x2<0><<<dim3(Hn, Mtot / 128), 256>>>(xk, Wk, bk, nullptr, 1);
    gemm_f32x2<0><<<dim3(Hn, Mtot / 128), 256>>>(xv, Wv, bv, nullptr, 2);

    // 2) scores = QK^T / 8, query-row-masked -> g_S
    scores_kernel<<<dim3(Sn / 64, Sn / 64, Bn * Hn), 256>>>(len);

    // 3) softmax over keys, in place
    softmax_kernel<<<Bn * Hn * Sn, 128>>>();

    // 4) context = P @ V -> g_C in [B,S,D] (heads concatenated)
    gemm_f32x2<1><<<dim3(Sn / 128, Bn * Hn), 256>>>(nullptr, nullptr, nullptr, nullptr, 0);

    // 5) out = context @ Wo + bo
    gemm_f32x2<2><<<dim3(Dn / 64, Mtot / 128), 256>>>(nullptr, Wo, bo, out, 0);
}

// round 15
// speedup vs baseline: 1.0023x; 1.0007x over previous
#include <cuda_runtime.h>
#include <cuda_bf16.h>
#include <cstdint>

// Problem constants
#define Bn  4
#define Sn  1024
#define Dn  1024
#define Hn  16
#define DHn 64
#define Mtot (Bn * Sn)   // 4096

// Scratch (device globals: allocation is forbidden)
__device__ __align__(16) float g_Q[(size_t)Bn * Hn * Sn * DHn];   // [B,H,S,DH]
__device__ __align__(16) float g_K[(size_t)Bn * Hn * Sn * DHn];
__device__ __align__(16) float g_V[(size_t)Bn * Hn * Sn * DHn];
__device__ __align__(16) float g_S[(size_t)Bn * Hn * Sn * Sn];    // scores/probs [B,H,S,S] (256MB)
__device__ __align__(16) float g_C[(size_t)Bn * Sn * Dn];         // context [B,S,D]

// ---- packed f32x2 helpers (sm_103a) ----
#define PACK2(dst, x) asm("mov.b64 %0, {%1, %2};" : "=l"(dst) : "f"(x), "f"(x))
#define FMA2(acc, a, b) asm("fma.rn.f32x2 %0, %1, %2, %0;" : "+l"(acc) : "l"(a), "l"(b))

__device__ __forceinline__ float lo32(unsigned long long u) {
    return __uint_as_float((unsigned)(u & 0xffffffffull));
}
__device__ __forceinline__ float hi32(unsigned long long u) {
    return __uint_as_float((unsigned)(u >> 32));
}

// ============================================================================
// Generic 128x64-tile fp32 GEMM using packed FFMA2.
// MODE 0: QKV projection. grid = (H=16, Mtot/128=32). A = x [4096,1024],
//         B = W + h*D*DH (row stride 64), C = g_Q/g_K/g_V per `sel`,
//         layout [B,H,S,DH], bias bq[h*64+n].
// MODE 1: AV. grid = (S/128=8, B*H=64). A = g_S[bh] [1024,1024],
//         B = g_V[bh] [1024,64], C = g_C [B,S,D] at column h*64.
// MODE 2: output projection. grid = (D/64=16, Mtot/128=32). A = g_C,
//         B = Wo (ldb=1024), C = d_out, bias bo.
// ============================================================================
template <int MODE>
__global__ void __launch_bounds__(256, 2) gemm_f32x2(
    const float* __restrict__ Ain, const float* __restrict__ Bin,
    const float* __restrict__ bias, float* __restrict__ Cout, int sel)
{
    const int tid = threadIdx.x;

    int mt, bh = 0, h = 0, nt = 0;
    const float* Aptr;
    const float* Bptr;
    int ldb;
    if (MODE == 0) {
        h = blockIdx.x; mt = blockIdx.y;
        Aptr = Ain;
        Bptr = Bin + (size_t)h * Dn * DHn;
        ldb = DHn;
    } else if (MODE == 1) {
        mt = blockIdx.x; bh = blockIdx.y;
        Aptr = g_S + (size_t)bh * Sn * Sn;
        Bptr = g_V + (size_t)bh * Sn * DHn;
        ldb = DHn;
    } else {
        nt = blockIdx.x; mt = blockIdx.y;
        Aptr = g_C;
        Bptr = Bin + nt * 64;
        ldb = Dn;
    }
    const int lda = 1024;  // all A matrices here have 1024 columns

    __shared__ __align__(16) float As[16][132];  // transposed A tile [k][m], padded
    __shared__ __align__(16) float Bs[16][64];

    const int ty = tid >> 4;        // 0..15 -> m offset ty*8
    const int tx = tid & 15;        // 0..15 -> n offset tx*4

    unsigned long long acc[4][4];
#pragma unroll
    for (int i = 0; i < 4; i++)
#pragma unroll
        for (int j = 0; j < 4; j++) acc[i][j] = 0ull;

    const int m0 = mt * 128;
    const int arow = tid >> 2;          // 0..63
    const int acol = (tid & 3) * 4;     // 0,4,8,12
    const int brow = tid >> 4;          // 0..15
    const int bcol = (tid & 15) * 4;    // 0..60

    for (int k0 = 0; k0 < 1024; k0 += 16) {
        // Load A tile (128x16), store transposed into As[k][m]
#pragma unroll
        for (int p = 0; p < 2; p++) {
            const int r = arow + p * 64;
            float4 v = *reinterpret_cast<const float4*>(
                &Aptr[(size_t)(m0 + r) * lda + k0 + acol]);
            As[acol + 0][r] = v.x;
            As[acol + 1][r] = v.y;
            As[acol + 2][r] = v.z;
            As[acol + 3][r] = v.w;
        }
        // Load B tile (16x64)
        {
            float4 w = *reinterpret_cast<const float4*>(
                &Bptr[(size_t)(k0 + brow) * ldb + bcol]);
            *reinterpret_cast<float4*>(&Bs[brow][bcol]) = w;
        }
        __syncthreads();

#pragma unroll
        for (int k = 0; k < 16; k++) {
            ulonglong2 a01 = *reinterpret_cast<const ulonglong2*>(&As[k][ty * 8]);
            ulonglong2 a23 = *reinterpret_cast<const ulonglong2*>(&As[k][ty * 8 + 4]);
            float4 bv = *reinterpret_cast<const float4*>(&Bs[k][tx * 4]);
            unsigned long long b0, b1, b2, b3;
            PACK2(b0, bv.x); PACK2(b1, bv.y); PACK2(b2, bv.z); PACK2(b3, bv.w);
            FMA2(acc[0][0], a01.x, b0); FMA2(acc[0][1], a01.x, b1);
            FMA2(acc[0][2], a01.x, b2); FMA2(acc[0][3], a01.x, b3);
            FMA2(acc[1][0], a01.y, b0); FMA2(acc[1][1], a01.y, b1);
            FMA2(acc[1][2], a01.y, b2); FMA2(acc[1][3], a01.y, b3);
            FMA2(acc[2][0], a23.x, b0); FMA2(acc[2][1], a23.x, b1);
            FMA2(acc[2][2], a23.x, b2); FMA2(acc[2][3], a23.x, b3);
            FMA2(acc[3][0], a23.y, b0); FMA2(acc[3][1], a23.y, b1);
            FMA2(acc[3][2], a23.y, b2); FMA2(acc[3][3], a23.y, b3);
        }
        __syncthreads();
    }

    // bias (MODE 0 and 2)
    float4 bias4 = make_float4(0.f, 0.f, 0.f, 0.f);
    if (MODE == 0)
        bias4 = *reinterpret_cast<const float4*>(&bias[h * 64 + tx * 4]);
    else if (MODE == 2)
        bias4 = *reinterpret_cast<const float4*>(&bias[nt * 64 + tx * 4]);

    // Epilogue: 8 rows x 4 cols per thread; acc[i2] holds row pair (2*i2, 2*i2+1)
#pragma unroll
    for (int i2 = 0; i2 < 4; i2++) {
        const int rloc = ty * 8 + i2 * 2;
        float4 row_lo = make_float4(lo32(acc[i2][0]) + bias4.x,
                                    lo32(acc[i2][1]) + bias4.y,
                                    lo32(acc[i2][2]) + bias4.z,
                                    lo32(acc[i2][3]) + bias4.w);
        float4 row_hi = make_float4(hi32(acc[i2][0]) + bias4.x,
                                    hi32(acc[i2][1]) + bias4.y,
                                    hi32(acc[i2][2]) + bias4.z,
                                    hi32(acc[i2][3]) + bias4.w);
        if (MODE == 0) {
            float* dst = (sel == 0) ? g_Q : (sel == 1) ? g_K : g_V;
            const int m_a = m0 + rloc;
            const int b_a = m_a >> 10, s_a = m_a & 1023;
            const int m_b = m_a + 1;
            const int b_b = m_b >> 10, s_b = m_b & 1023;
            size_t ia = (((size_t)(b_a * Hn + h) * Sn + s_a) << 6) + tx * 4;
            size_t ib = (((size_t)(b_b * Hn + h) * Sn + s_b) << 6) + tx * 4;
            *reinterpret_cast<float4*>(&dst[ia]) = row_lo;
            *reinterpret_cast<float4*>(&dst[ib]) = row_hi;
        } else if (MODE == 1) {
            const int b = bh >> 4, hh = bh & 15;
            const int s = m0 + rloc;
            size_t ia = ((size_t)(b * Sn + s)) * Dn + hh * 64 + tx * 4;
            size_t ib = ((size_t)(b * Sn + s + 1)) * Dn + hh * 64 + tx * 4;
            *reinterpret_cast<float4*>(&g_C[ia]) = row_lo;
            *reinterpret_cast<float4*>(&g_C[ib]) = row_hi;
        } else {
            const int m = m0 + rloc;
            size_t ia = (size_t)m * Dn + nt * 64 + tx * 4;
            size_t ib = (size_t)(m + 1) * Dn + nt * 64 + tx * 4;
            *reinterpret_cast<float4*>(&Cout[ia]) = row_lo;
            *reinterpret_cast<float4*>(&Cout[ib]) = row_hi;
        }
    }
}

// ============================================================================
// scores[s][t] = dot(Q[bh,s,:], K[bh,t,:]) * 0.125, zeroed for s >= len[b].
// grid = (16 t-tiles, 16 s-tiles, B*H). 64x64 output tile, full K=64 in smem.
// ============================================================================
__global__ void __launch_bounds__(256, 2) scores_kernel(const int* __restrict__ lens)
{
    const int tid = threadIdx.x;
    const int bh = blockIdx.z;
    const int b = bh >> 4;
    const int st = blockIdx.y, tt = blockIdx.x;

    const float* Qb = g_Q + ((size_t)bh * Sn + st * 64) * DHn;
    const float* Kb = g_K + ((size_t)bh * Sn + tt * 64) * DHn;

    __shared__ __align__(16) float Qs[64][68];  // transposed [e][s]
    __shared__ __align__(16) float Ks[64][68];  // transposed [e][t]

    const int lr = tid >> 4;         // 0..15
    const int lc = (tid & 15) * 4;   // 0..60
#pragma unroll
    for (int p = 0; p < 4; p++) {
        const int r = lr + p * 16;
        float4 q = *reinterpret_cast<const float4*>(&Qb[r * 64 + lc]);
        Qs[lc + 0][r] = q.x; Qs[lc + 1][r] = q.y;
        Qs[lc + 2][r] = q.z; Qs[lc + 3][r] = q.w;
        float4 kk = *reinterpret_cast<const float4*>(&Kb[r * 64 + lc]);
        Ks[lc + 0][r] = kk.x; Ks[lc + 1][r] = kk.y;
        Ks[lc + 2][r] = kk.z; Ks[lc + 3][r] = kk.w;
    }
    __syncthreads();

    const int s0 = (tid >> 4) * 4;  // 0..60
    const int t0 = (tid & 15) * 4;  // 0..60

    unsigned long long acc[2][4];
#pragma unroll
    for (int i = 0; i < 2; i++)
#pragma unroll
        for (int j = 0; j < 4; j++) acc[i][j] = 0ull;

#pragma unroll 16
    for (int k = 0; k < 64; k++) {
        ulonglong2 aa = *reinterpret_cast<const ulonglong2*>(&Qs[k][s0]);
        float4 kv = *reinterpret_cast<const float4*>(&Ks[k][t0]);
        unsigned long long b0, b1, b2, b3;
        PACK2(b0, kv.x); PACK2(b1, kv.y); PACK2(b2, kv.z); PACK2(b3, kv.w);
        FMA2(acc[0][0], aa.x, b0); FMA2(acc[0][1], aa.x, b1);
        FMA2(acc[0][2], aa.x, b2); FMA2(acc[0][3], aa.x, b3);
        FMA2(acc[1][0], aa.y, b0); FMA2(acc[1][1], aa.y, b1);
        FMA2(acc[1][2], aa.y, b2); FMA2(acc[1][3], aa.y, b3);
    }

    const int len = lens[b];
    float* outbase = g_S + ((size_t)bh << 20) + (size_t)tt * 64 + t0;
#pragma unroll
    for (int i2 = 0; i2 < 2; i2++) {
        const int r_lo = s0 + i2 * 2;
        const int sg_lo = st * 64 + r_lo;
        const int sg_hi = sg_lo + 1;
        const float sc_lo = (sg_lo < len) ? 0.125f : 0.0f;
        const float sc_hi = (sg_hi < len) ? 0.125f : 0.0f;
        float4 v_lo = make_float4(lo32(acc[i2][0]) * sc_lo, lo32(acc[i2][1]) * sc_lo,
                                  lo32(acc[i2][2]) * sc_lo, lo32(acc[i2][3]) * sc_lo);
        float4 v_hi = make_float4(hi32(acc[i2][0]) * sc_hi, hi32(acc[i2][1]) * sc_hi,
                                  hi32(acc[i2][2]) * sc_hi, hi32(acc[i2][3]) * sc_hi);
        *reinterpret_cast<float4*>(&outbase[(size_t)sg_lo * Sn]) = v_lo;
        *reinterpret_cast<float4*>(&outbase[(size_t)sg_hi * Sn]) = v_hi;
    }
}

// ============================================================================
// Row softmax over 1024 keys, in place in g_S. One block (128 thr) per row.
// Masked rows are all-zero -> max 0, exp 1, sum 1024 -> uniform 1/1024,
// exactly matching the reference (mask-then-softmax).
// ============================================================================
__global__ void __launch_bounds__(128) softmax_kernel()
{
    const int tid = threadIdx.x;
    float4* p = reinterpret_cast<float4*>(g_S + (size_t)blockIdx.x * Sn);
    float4 v0 = p[tid];
    float4 v1 = p[tid + 128];

    float m = fmaxf(fmaxf(fmaxf(v0.x, v0.y), fmaxf(v0.z, v0.w)),
                    fmaxf(fmaxf(v1.x, v1.y), fmaxf(v1.z, v1.w)));
#pragma unroll
    for (int o = 16; o > 0; o >>= 1)
        m = fmaxf(m, __shfl_xor_sync(0xffffffffu, m, o));

    __shared__ float redm[4];
    __shared__ float reds[4];
    const int w = tid >> 5;
    if ((tid & 31) == 0) redm[w] = m;
    __syncthreads();
    m = fmaxf(fmaxf(redm[0], redm[1]), fmaxf(redm[2], redm[3]));

    v0.x = __expf(v0.x - m); v0.y = __expf(v0.y - m);
    v0.z = __expf(v0.z - m); v0.w = __expf(v0.w - m);
    v1.x = __expf(v1.x - m); v1.y = __expf(v1.y - m);
    v1.z = __expf(v1.z - m); v1.w = __expf(v1.w - m);

    float s = (v0.x + v0.y) + (v0.z + v0.w) + (v1.x + v1.y) + (v1.z + v1.w);
#pragma unroll
    for (int o = 16; o > 0; o >>= 1)
        s += __shfl_xor_sync(0xffffffffu, s, o);
    if ((tid & 31) == 0) reds[w] = s;
    __syncthreads();
    s = (reds[0] + reds[1]) + (reds[2] + reds[3]);

    const float inv = 1.0f / s;
    v0.x *= inv; v0.y *= inv; v0.z *= inv; v0.w *= inv;
    v1.x *= inv; v1.y *= inv; v1.z *= inv; v1.w *= inv;
    p[tid] = v0;
    p[tid + 128] = v1;
}

// ============================================================================
extern "C" void kernel_launch(void* const* d_in, const int* in_sizes, int n_in,
                              void* d_out, int out_size)
{
    const float* xq  = (const float*)d_in[0];
    const float* xk  = (const float*)d_in[1];
    const float* xv  = (const float*)d_in[2];
    const int*   len = (const int*)  d_in[3];
    const float* Wq  = (const float*)d_in[4];
    const float* bq  = (const float*)d_in[5];
    const float* Wk  = (const float*)d_in[6];
    const float* bk  = (const float*)d_in[7];
    const float* Wv  = (const float*)d_in[8];
    const float* bv  = (const float*)d_in[9];
    const float* Wo  = (const float*)d_in[10];
    const float* bo  = (const float*)d_in[11];
    float* out = (float*)d_out;

    // 1) Q/K/V projections -> g_Q/g_K/g_V in [B,H,S,DH]
    gemm_f32x2<0><<<dim3(Hn, Mtot / 128), 256>>>(xq, Wq, bq, nullptr, 0);
    gemm_f32x2<0><<<dim3(Hn, Mtot / 128), 256>>>(xk, Wk, bk, nullptr, 1);
    gemm_f32x2<0><<<dim3(Hn, Mtot / 128), 256>>>(xv, Wv, bv, nullptr, 2);

    // 2) scores = QK^T / 8, query-row-masked -> g_S
    scores_kernel<<<dim3(Sn / 64, Sn / 64, Bn * Hn), 256>>>(len);

    // 3) softmax over keys, in place
    softmax_kernel<<<Bn * Hn * Sn, 128>>>();

    // 4) context = P @ V -> g_C in [B,S,D] (heads concatenated)
    gemm_f32x2<1><<<dim3(Sn / 128, Bn * Hn), 256>>>(nullptr, nullptr, nullptr, nullptr, 0);

    // 5) out = context @ Wo + bo
    gemm_f32x2<2><<<dim3(Dn / 64, Mtot / 128), 256>>>(nullptr, Wo, bo, out, 0);
}